// round 17
// baseline (speedup 1.0000x reference)
#include <cuda_runtime.h>
#include <cstdint>

typedef unsigned long long u64;
typedef unsigned int u32;

#define N_ENT   50000
#define N_EDGES 800000
#define NQ      (N_EDGES/4)    // 200000 edge quads (int4 path, gated rounds)
#define NP      (N_EDGES/2)    // 400000 edge pairs (int2 path, dense rounds)
#define D_PE    16
#define NW32    1564           // ceil(50000/32), == 391*4

#define GN      196            // node blocks (256 thr): 196*256 = 50176
#define GEP     1563           // dense edge blocks (256 thr, 2 edges/thread)
#define GE512   391            // gated edge blocks (512 thr, 4 edges/thread)
#define GF512   98             // fold blocks (512 thr): 98*512 = 50176

// ---- device state (no allocations allowed) --------------------------------
// Replay-invariant protocol: BSS zero gives call 1 its clean state; each
// call's k_final restores P_1.x = 0 and Fbm = 0 for the next call. Seeds are
// rebuilt from inputs (pre-PDL-wait) by every block that needs them.
// P_d[n].x = next_d bits (round-d atomics; zeroed by fold_{d-1} / final)
// P_d[n].y = vis_{d-1} bits (stored by fold_d)
// Round d>=2 reads only completed P_{d-1}: front = x&~y, vis = x|y.
__device__ ulonglong2 g_P[5][N_ENT];      // index 0 unused
__device__ u64 g_cnt[N_ENT];    // packed byte counts c0|c1<<8|c2<<16|c3<<24
__device__ u32 g_Fbm[NW32];     // round-2 gate: round-1 push targets

__device__ __forceinline__ ulonglong2 ldp(const ulonglong2* p) {
    ulonglong2 r;
    asm volatile("ld.global.v2.u64 {%0,%1}, [%2];"
                 : "=l"(r.x), "=l"(r.y) : "l"(p));
    return r;
}
__device__ __forceinline__ void pdl_wait() {
    asm volatile("griddepcontrol.wait;" ::: "memory");
}
__device__ __forceinline__ void pdl_release() {
    asm volatile("griddepcontrol.launch_dependents;" ::: "memory");
}

// Load the 64 seed candidates (inputs only -> pre-wait safe).
__device__ __forceinline__ void load_seed_vals(int* svals, int tid,
                                               const int* __restrict__ h,
                                               const int* __restrict__ t,
                                               const int* __restrict__ aidx) {
    if (tid < 64) {
        int e = __ldg(aidx + (tid & 31));
        svals[tid] = (tid < 32) ? __ldg(h + e) : __ldg(t + e);
    }
}
__device__ __forceinline__ int first_slot(const int* svals, int v) {
    for (int j = 0; j < 64; j++) if (svals[j] == v) return j;
    return 0;
}

// Generic fold for depth d>=2 (inputs: completed P_{d-1}).
__device__ __forceinline__ void do_fold(int d, int n) {
    if (n >= N_ENT) return;
    ulonglong2 p = ldp(&g_P[d-1][n]);
    g_P[d][n].y = p.x | p.y;                 // vis_{d-1}
    if (d < 4) g_P[d+1][n].x = 0ull;
    u64 newly = p.x & ~p.y;
    if (newly) g_cnt[n] += (u64)__popcll(newly) << (8 * (d - 1));
}

// ---------------------------------------------------------------------------
// Round 1 — critical path ~0: the ENTIRE edge scan runs pre-wait (inputs
// only); post-wait flushes only the rare seed-adjacent pushes (~4K atomics).
// Fold blocks write P1.y (seed vis, input-derived) and P2.x=0 pre-wait
// (previous call's final touches neither); only the c0 store is post-wait
// (it races with final's g_cnt read).
__global__ void __launch_bounds__(512)
k_round1(const int* __restrict__ h, const int* __restrict__ t,
         const int* __restrict__ aidx) {
    __shared__ int svals[64];
    __shared__ u32 sBM[NW32];
    const int tid = threadIdx.x;
    const int blk = blockIdx.x;
    const bool isEdge = (blk >= GF512);

    // ---- pre-wait: inputs only -------------------------------------------
    load_seed_vals(svals, tid, h, t, aidx);
    for (int i = tid; i < NW32; i += 512) sBM[i] = 0u;
    int j = 0; bool act = false; int4 S, D;
    if (isEdge) {
        j = (blk - GF512) * 512 + tid;
        act = (j < NQ);
        if (act) {
            S = __ldg((const int4*)h + j);
            D = __ldg((const int4*)t + j);
        }
    }
    __syncthreads();
    if (tid < 64) {
        int v = svals[tid];
        atomicOr(&sBM[((u32)v) >> 5], 1u << (v & 31));
    }
    __syncthreads();

    u32 hm = 0;                // per-thread hit mask: bit 2q=fS, 2q+1=fD
    u32 w = 0;                 // fold: seed membership
    int n = 0;
    if (isEdge) {
        if (act) {
            #pragma unroll
            for (int q = 0; q < 4; q++) {
                int s = (q == 0) ? S.x : (q == 1) ? S.y : (q == 2) ? S.z : S.w;
                int e = (q == 0) ? D.x : (q == 1) ? D.y : (q == 2) ? D.z : D.w;
                hm |= ((sBM[s >> 5] >> (s & 31)) & 1u) << (2 * q);
                hm |= ((sBM[e >> 5] >> (e & 31)) & 1u) << (2 * q + 1);
            }
        }
    } else {
        n = blk * 512 + tid;
        if (n < N_ENT) {
            w = (sBM[n >> 5] >> (n & 31)) & 1u;
            u64 vis0 = w ? (1ull << first_slot(svals, n)) : 0ull;
            g_P[1][n].y = vis0;          // pre-wait safe (see header comment)
            g_P[2][n].x = 0ull;
        }
    }

    pdl_wait();
    pdl_release();

    // ---- post-wait: only successor-state writes --------------------------
    if (isEdge) {
        if (hm) {
            #pragma unroll
            for (int q = 0; q < 4; q++) {
                int s = (q == 0) ? S.x : (q == 1) ? S.y : (q == 2) ? S.z : S.w;
                int e = (q == 0) ? D.x : (q == 1) ? D.y : (q == 2) ? D.z : D.w;
                if ((hm >> (2 * q)) & 1u) {
                    u64 bit = 1ull << first_slot(svals, s);
                    atomicOr(&g_P[1][e].x, bit);
                    atomicOr(&g_Fbm[e >> 5], 1u << (e & 31));
                }
                if ((hm >> (2 * q + 1)) & 1u) {
                    u64 bit = 1ull << first_slot(svals, e);
                    atomicOr(&g_P[1][s].x, bit);
                    atomicOr(&g_Fbm[s >> 5], 1u << (s & 31));
                }
            }
        }
    } else {
        if (n < N_ENT) g_cnt[n] = (u64)w;    // c0 (after final's g_cnt read)
    }
}

// ---------------------------------------------------------------------------
// Round 2: gate on g_Fbm (round-1 targets); exact pair reads + dedup'd ORs.
__global__ void __launch_bounds__(512)
k_round2(const int* __restrict__ h, const int* __restrict__ t) {
    __shared__ u32 sF[NW32];
    const int tid = threadIdx.x;
    const int blk = blockIdx.x;
    const ulonglong2* __restrict__ Pp = g_P[1];

    if (blk >= GF512) {
        const int j = (blk - GF512) * 512 + tid;
        const bool act = (j < NQ);
        int4 S, D;
        if (act) {                            // inputs only: pre-wait safe
            S = __ldg((const int4*)h + j);
            D = __ldg((const int4*)t + j);
        }
        pdl_wait();
        pdl_release();
        if (tid < NW32 / 4)
            ((uint4*)sF)[tid] = __ldcg((const uint4*)g_Fbm + tid);
        __syncthreads();
        if (!act) return;

        #pragma unroll
        for (int q = 0; q < 4; q++) {
            int s = (q == 0) ? S.x : (q == 1) ? S.y : (q == 2) ? S.z : S.w;
            int e = (q == 0) ? D.x : (q == 1) ? D.y : (q == 2) ? D.z : D.w;
            u32 fS = (sF[s >> 5] >> (s & 31)) & 1u;
            u32 fD = (sF[e >> 5] >> (e & 31)) & 1u;
            if (fS | fD) {
                ulonglong2 a = ldp(&Pp[s]);
                ulonglong2 b = ldp(&Pp[e]);
                if (fS) { u64 nb = (a.x & ~a.y) & ~(b.x | b.y);
                          if (nb) atomicOr(&g_P[2][e].x, nb); }
                if (fD) { u64 nb = (b.x & ~b.y) & ~(a.x | a.y);
                          if (nb) atomicOr(&g_P[2][s].x, nb); }
            }
        }
    } else {
        pdl_wait();
        pdl_release();
        do_fold(2, blk * 512 + tid);
    }
}

// ---------------------------------------------------------------------------
// Dense rounds (3-4): 2 edges/thread (int2), 4 batched gathers. Round 3
// keeps the dedup mask (skips ~30% of atomics); round 4 pushes the raw front
// (atomics fire ~always; k_final masks by ~vis_3 exactly).
__global__ void __launch_bounds__(256)
k_round_dense(int d, const int* __restrict__ h, const int* __restrict__ t) {
    const int tid = threadIdx.x;
    const int blk = blockIdx.x;
    const ulonglong2* __restrict__ Pp = g_P[d - 1];
    ulonglong2* Pc = g_P[d];

    if (blk >= GN) {
        const int g = (blk - GN) * 256 + tid;
        const bool act = (g < NP);
        int2 S, D;
        if (act) {                            // inputs only: pre-wait safe
            S = __ldg((const int2*)h + g);
            D = __ldg((const int2*)t + g);
        }
        pdl_wait();
        pdl_release();
        if (!act) return;

        ulonglong2 a0 = ldp(&Pp[S.x]);
        ulonglong2 b0 = ldp(&Pp[D.x]);
        ulonglong2 a1 = ldp(&Pp[S.y]);
        ulonglong2 b1 = ldp(&Pp[D.y]);

        u64 nb;
        if (d == 4) {                         // saturated: dedup not worth it
            nb = a0.x & ~a0.y; if (nb) atomicOr(&Pc[D.x].x, nb);
            nb = b0.x & ~b0.y; if (nb) atomicOr(&Pc[S.x].x, nb);
            nb = a1.x & ~a1.y; if (nb) atomicOr(&Pc[D.y].x, nb);
            nb = b1.x & ~b1.y; if (nb) atomicOr(&Pc[S.y].x, nb);
        } else {
            nb = (a0.x & ~a0.y) & ~(b0.x | b0.y); if (nb) atomicOr(&Pc[D.x].x, nb);
            nb = (b0.x & ~b0.y) & ~(a0.x | a0.y); if (nb) atomicOr(&Pc[S.x].x, nb);
            nb = (a1.x & ~a1.y) & ~(b1.x | b1.y); if (nb) atomicOr(&Pc[D.y].x, nb);
            nb = (b1.x & ~b1.y) & ~(a1.x | a1.y); if (nb) atomicOr(&Pc[S.y].x, nb);
        }
    } else {
        pdl_wait();
        pdl_release();
        do_fold(d, blk * 256 + tid);
    }
}

// ---------------------------------------------------------------------------
// Final: depth-4 count + embedding combine; computes nvalid from inputs
// (pre-wait); restores the next call's invariant (P_1.x=0, Fbm=0).
__global__ void __launch_bounds__(256)
k_final(const float* __restrict__ embed, float* __restrict__ out,
        const int* __restrict__ h, const int* __restrict__ t,
        const int* __restrict__ aidx) {
    __shared__ float sE[6 * D_PE];
    __shared__ int svals[64];
    __shared__ int scnt;
    const int tid = threadIdx.x;

    // ---- pre-wait: inputs only ----
    if (tid < 6 * D_PE) sE[tid] = __ldg(embed + tid);
    if (tid == 0) scnt = 0;
    load_seed_vals(svals, tid, h, t, aidx);
    __syncthreads();
    if (tid < 64) {
        int v = svals[tid];
        bool uniq = true;
        for (int j = 0; j < tid; j++) if (svals[j] == v) uniq = false;
        u32 bal = __ballot_sync(0xffffffffu, uniq);
        if ((tid & 31) == 0) atomicAdd(&scnt, (int)__popc(bal));
    }
    __syncthreads();
    const int nv = scnt;

    pdl_wait();
    pdl_release();

    int n = blockIdx.x * 256 + tid;
    if (n >= N_ENT) return;

    // restore invariant for the next call
    g_P[1][n].x = 0ull;
    if (n < NW32) g_Fbm[n] = 0u;

    ulonglong2 p = ldp(&g_P[4][n]);          // {next_4, vis_3}
    u64 c  = __ldg(&g_cnt[n]);
    int c4 = __popcll(p.x & ~p.y);
    int c0 = (int)( c        & 0xFF);
    int c1 = (int)((c >> 8)  & 0xFF);
    int c2 = (int)((c >> 16) & 0xFF);
    int c3 = (int)((c >> 24) & 0xFF);
    int rem = nv - (c0 + c1 + c2 + c3 + c4);
    float inv = 1.0f / (float)nv;
    float w0 = c0 * inv, w1 = c1 * inv, w2 = c2 * inv;
    float w3 = c3 * inv, w4 = c4 * inv, w5 = rem * inv;

    float4* o = (float4*)(out + (size_t)n * D_PE);
#pragma unroll
    for (int q = 0; q < 4; q++) {
        float4 r;
        int b = q * 4;
        r.x = w0*sE[b+0] + w1*sE[D_PE+b+0] + w2*sE[2*D_PE+b+0]
            + w3*sE[3*D_PE+b+0] + w4*sE[4*D_PE+b+0] + w5*sE[5*D_PE+b+0];
        r.y = w0*sE[b+1] + w1*sE[D_PE+b+1] + w2*sE[2*D_PE+b+1]
            + w3*sE[3*D_PE+b+1] + w4*sE[4*D_PE+b+1] + w5*sE[5*D_PE+b+1];
        r.z = w0*sE[b+2] + w1*sE[D_PE+b+2] + w2*sE[2*D_PE+b+2]
            + w3*sE[3*D_PE+b+2] + w4*sE[4*D_PE+b+2] + w5*sE[5*D_PE+b+2];
        r.w = w0*sE[b+3] + w1*sE[D_PE+b+3] + w2*sE[2*D_PE+b+3]
            + w3*sE[3*D_PE+b+3] + w4*sE[4*D_PE+b+3] + w5*sE[5*D_PE+b+3];
        o[q] = r;
    }
}

// ---------------------------------------------------------------------------
template <typename... Args>
static inline void launch_pdl(void (*kern)(Args...), dim3 grid, dim3 block,
                              Args... args) {
    cudaLaunchAttribute attr;
    attr.id = cudaLaunchAttributeProgrammaticStreamSerialization;
    attr.val.programmaticStreamSerializationAllowed = 1;
    cudaLaunchConfig_t cfg = {};
    cfg.gridDim  = grid;
    cfg.blockDim = block;
    cfg.dynamicSmemBytes = 0;
    cfg.stream   = 0;
    cfg.attrs    = &attr;
    cfg.numAttrs = 1;
    cudaLaunchKernelEx(&cfg, kern, args...);
}

extern "C" void kernel_launch(void* const* d_in, const int* in_sizes, int n_in,
                              void* d_out, int out_size) {
    const int*   h     = (const int*)d_in[0];   // [800000]
    const int*   t     = (const int*)d_in[1];   // [800000]
    const int*   aidx  = (const int*)d_in[2];   // [32]
    const float* embed = (const float*)d_in[4]; // [6,16]
    float*       out   = (float*)d_out;         // [50000,16]

    const dim3 B256(256), B512(512);

    launch_pdl(k_round1, dim3(GF512 + GE512), B512, h, t, aidx);   // depth 1
    launch_pdl(k_round2, dim3(GF512 + GE512), B512, h, t);         // depth 2
    launch_pdl(k_round_dense, dim3(GN + GEP), B256, 3, h, t);      // depth 3
    launch_pdl(k_round_dense, dim3(GN + GEP), B256, 4, h, t);      // depth 4
    launch_pdl(k_final, dim3(GN), B256, embed, out, h, t, aidx);   // output
}